// round 4
// baseline (speedup 1.0000x reference)
#include <cuda_runtime.h>

// BinStats_27401891348536 fixed shapes:
// x: [64, 512, 28, 28] f32; bin_edges: [512, 11]; feature_ranges: [512];
// bin_counts: [512, 10]; out = bin_counts + per-channel histogram of x/range.
#define C_     512
#define NB_    10
#define NEDGE_ 11
#define NF4_   196            // 28*28/4 float4 per row
#define NWARP_ 2048           // multiple of 512 -> channel constant per warp
#define RPW_   16             // rows per warp (32768 / 2048)

__global__ void init_out_kernel(const float* __restrict__ bc,
                                float* __restrict__ out, int n) {
    int i = blockIdx.x * blockDim.x + threadIdx.x;
    if (i < n) out[i] = bc[i];
}

// searchsorted(inner, v, 'left') with uniform inner edges s_k = s0 + k*D:
// count of edges < x == clamp(ceil((x - s0)/D), 0, 9)
__device__ __forceinline__ unsigned long long bump(float x, float invD, float c0) {
    float u = fmaf(x, invD, c0);
    u = fminf(fmaxf(u, 0.0f), 9.0f);
    int b = __float2int_ru(u);
    return 1ULL << (6 * b);
}

__device__ __forceinline__ void load_row(float4 v[7], const float4* __restrict__ p,
                                         int lane, bool tail) {
    v[0] = __ldg(p +   0 + lane);
    v[1] = __ldg(p +  32 + lane);
    v[2] = __ldg(p +  64 + lane);
    v[3] = __ldg(p +  96 + lane);
    v[4] = __ldg(p + 128 + lane);
    v[5] = __ldg(p + 160 + lane);
    if (tail) v[6] = __ldg(p + 192 + lane);
}

__device__ __forceinline__ void acc_row(const float4 v[7], bool tail,
                                        unsigned long long& a0, unsigned long long& a1,
                                        unsigned long long& a2, unsigned long long& a3,
                                        float invD, float c0) {
#pragma unroll
    for (int i = 0; i < 6; i++) {
        a0 += bump(v[i].x, invD, c0);
        a1 += bump(v[i].y, invD, c0);
        a2 += bump(v[i].z, invD, c0);
        a3 += bump(v[i].w, invD, c0);
    }
    if (tail) {
        a0 += bump(v[6].x, invD, c0);
        a1 += bump(v[6].y, invD, c0);
        a2 += bump(v[6].z, invD, c0);
        a3 += bump(v[6].w, invD, c0);
    }
}

__device__ __forceinline__ void flush_acc(unsigned long long& a0, unsigned long long& a1,
                                          unsigned long long& a2, unsigned long long& a3,
                                          unsigned cnt[NB_]) {
#pragma unroll
    for (int b = 0; b < NB_; b++) {
        const int sh = 6 * b;
        cnt[b] += ((unsigned)(a0 >> sh) & 63u)
                + ((unsigned)(a1 >> sh) & 63u)
                + ((unsigned)(a2 >> sh) & 63u)
                + ((unsigned)(a3 >> sh) & 63u);
    }
    a0 = a1 = a2 = a3 = 0ULL;
}

// One warp per block; 2048 blocks, 16 rows/warp, software-pipelined loads.
__global__ void __launch_bounds__(32, 20) hist_kernel(
    const float4* __restrict__ x4,
    const float*  __restrict__ bin_edges,
    const float*  __restrict__ fr,
    float*        __restrict__ out)
{
    const int lane = threadIdx.x;
    const int warp = blockIdx.x;
    const int c    = warp & (C_ - 1);
    const bool tail = (lane < 4);

    // Pre-scale by range: edge_k < x/range  <=>  edge_k*range < x
    const float range = __ldg(&fr[c]);
    const float s0 = __ldg(&bin_edges[c * NEDGE_ + 1]) * range;
    const float s8 = __ldg(&bin_edges[c * NEDGE_ + 9]) * range;
    const float invD = 8.0f / (s8 - s0);
    const float c0   = -s0 * invD;

    const float4* base = x4 + (size_t)warp * NF4_;
    const size_t rstride = (size_t)NWARP_ * NF4_;

    unsigned long long a0 = 0, a1 = 0, a2 = 0, a3 = 0;
    unsigned cnt[NB_];
#pragma unroll
    for (int b = 0; b < NB_; b++) cnt[b] = 0;

    float4 bufA[7], bufB[7];
    load_row(bufA, base, lane, tail);

    // Pipelined: load row k+1 before accumulating row k. 2 rows per iteration.
#pragma unroll
    for (int k = 0; k < RPW_; k += 2) {
        load_row(bufB, base + (size_t)(k + 1) * rstride, lane, tail);
        acc_row(bufA, tail, a0, a1, a2, a3, invD, c0);
        if (k + 2 < RPW_)
            load_row(bufA, base + (size_t)(k + 2) * rstride, lane, tail);
        acc_row(bufB, tail, a0, a1, a2, a3, invD, c0);
        if (k + 2 == RPW_ / 2)   // after 8 rows: fields <= 56 < 63, flush
            flush_acc(a0, a1, a2, a3, cnt);
    }
    flush_acc(a0, a1, a2, a3, cnt);

#pragma unroll
    for (int b = 0; b < NB_; b++) {
        unsigned tot = __reduce_add_sync(0xffffffffu, cnt[b]);
        if (lane == b) atomicAdd(out + c * NB_ + b, (float)tot);
    }
}

extern "C" void kernel_launch(void* const* d_in, const int* in_sizes, int n_in,
                              void* d_out, int out_size) {
    const float* x  = (const float*)d_in[0];
    const float* be = (const float*)d_in[1];
    const float* fr = (const float*)d_in[2];
    const float* bc = (const float*)d_in[3];
    float* out = (float*)d_out;

    init_out_kernel<<<(out_size + 255) / 256, 256>>>(bc, out, out_size);
    hist_kernel<<<NWARP_, 32>>>((const float4*)x, be, fr, out);
}

// round 5
// speedup vs baseline: 1.1098x; 1.1098x over previous
#include <cuda_runtime.h>

// BinStats_27401891348536 fixed shapes:
// x: [64, 512, 28, 28] f32; bin_edges: [512, 11]; feature_ranges: [512];
// bin_counts: [512, 10]; out = bin_counts + per-channel histogram of x/range.
#define C_     512
#define NB_    10
#define NEDGE_ 11
#define NF4_   196            // 28*28/4 float4 per row
#define ROWS_  32768
#define NWARP_ 3584           // 7*512 -> channel constant per warp; 24.2 blocks/SM
#define RFIX_  9              // fixed rows per warp (9*3584 = 32256)
// remaining 512 rows (32256..32767): row 32256+w belongs to channel w (32256%512==0)

__global__ void init_out_kernel(const float* __restrict__ bc,
                                float* __restrict__ out, int n) {
    int i = blockIdx.x * blockDim.x + threadIdx.x;
    if (i < n) out[i] = bc[i];
}

// searchsorted(inner, v, 'left') with uniform inner edges s_k = s0 + k*D:
// count of edges < x == clamp(ceil((x - s0)/D), 0, 9)
__device__ __forceinline__ unsigned long long bump(float x, float invD, float c0) {
    float u = fmaf(x, invD, c0);
    u = fminf(fmaxf(u, 0.0f), 9.0f);
    int b = __float2int_ru(u);
    return 1ULL << (6 * b);
}

__device__ __forceinline__ void load_row(float4 v[7], const float4* __restrict__ p,
                                         int lane, bool tail) {
    v[0] = __ldg(p +   0 + lane);
    v[1] = __ldg(p +  32 + lane);
    v[2] = __ldg(p +  64 + lane);
    v[3] = __ldg(p +  96 + lane);
    v[4] = __ldg(p + 128 + lane);
    v[5] = __ldg(p + 160 + lane);
    if (tail) v[6] = __ldg(p + 192 + lane);
}

__device__ __forceinline__ void acc_row(const float4 v[7], bool tail,
                                        unsigned long long& a0, unsigned long long& a1,
                                        unsigned long long& a2, unsigned long long& a3,
                                        float invD, float c0) {
#pragma unroll
    for (int i = 0; i < 6; i++) {
        a0 += bump(v[i].x, invD, c0);
        a1 += bump(v[i].y, invD, c0);
        a2 += bump(v[i].z, invD, c0);
        a3 += bump(v[i].w, invD, c0);
    }
    if (tail) {
        a0 += bump(v[6].x, invD, c0);
        a1 += bump(v[6].y, invD, c0);
        a2 += bump(v[6].z, invD, c0);
        a3 += bump(v[6].w, invD, c0);
    }
}

__device__ __forceinline__ void flush_acc(unsigned long long& a0, unsigned long long& a1,
                                          unsigned long long& a2, unsigned long long& a3,
                                          unsigned cnt[NB_]) {
#pragma unroll
    for (int b = 0; b < NB_; b++) {
        const int sh = 6 * b;
        cnt[b] += ((unsigned)(a0 >> sh) & 63u)
                + ((unsigned)(a1 >> sh) & 63u)
                + ((unsigned)(a2 >> sh) & 63u)
                + ((unsigned)(a3 >> sh) & 63u);
    }
    a0 = a1 = a2 = a3 = 0ULL;
}

// One warp per block; 3584 blocks; double-buffered, fully unrolled row pipeline.
// 24 blocks/SM -> 85-reg budget (estimated use ~78, no spill).
__global__ void __launch_bounds__(32, 24) hist_kernel(
    const float4* __restrict__ x4,
    const float*  __restrict__ bin_edges,
    const float*  __restrict__ fr,
    float*        __restrict__ out)
{
    const int lane = threadIdx.x;
    const int warp = blockIdx.x;
    const int c    = warp & (C_ - 1);
    const bool tail = (lane < 4);

    // Pre-scale by range: edge_k < x/range  <=>  edge_k*range < x
    const float range = __ldg(&fr[c]);
    const float s0 = __ldg(&bin_edges[c * NEDGE_ + 1]) * range;
    const float s8 = __ldg(&bin_edges[c * NEDGE_ + 9]) * range;
    const float invD = 8.0f / (s8 - s0);
    const float c0   = -s0 * invD;

    const float4* base = x4 + (size_t)warp * NF4_;
    const size_t rstride = (size_t)NWARP_ * NF4_;

    unsigned long long a0 = 0, a1 = 0, a2 = 0, a3 = 0;
    unsigned cnt[NB_];
#pragma unroll
    for (int b = 0; b < NB_; b++) cnt[b] = 0;

    float4 A[7], B[7];
    load_row(A, base, lane, tail);

    // 9 rows, pipelined: prefetch row k+1 while binning row k.
    // Max increments per 6-bit field per acc = 9*7 = 63, exactly fits.
#pragma unroll
    for (int k = 0; k < RFIX_; k++) {
        if (k + 1 < RFIX_)
            load_row((k & 1) ? A : B, base + (size_t)(k + 1) * rstride, lane, tail);
        if (k & 1) acc_row(B, tail, a0, a1, a2, a3, invD, c0);
        else       acc_row(A, tail, a0, a1, a2, a3, invD, c0);
    }
    flush_acc(a0, a1, a2, a3, cnt);

    // Extra row for the first 512 warps (row 32256+warp, same channel).
    if (warp < C_) {
        load_row(A, x4 + (size_t)(RFIX_ * NWARP_ + warp) * NF4_, lane, tail);
        acc_row(A, tail, a0, a1, a2, a3, invD, c0);
        flush_acc(a0, a1, a2, a3, cnt);
    }

#pragma unroll
    for (int b = 0; b < NB_; b++) {
        unsigned tot = __reduce_add_sync(0xffffffffu, cnt[b]);
        if (lane == b) atomicAdd(out + c * NB_ + b, (float)tot);
    }
}

extern "C" void kernel_launch(void* const* d_in, const int* in_sizes, int n_in,
                              void* d_out, int out_size) {
    const float* x  = (const float*)d_in[0];
    const float* be = (const float*)d_in[1];
    const float* fr = (const float*)d_in[2];
    const float* bc = (const float*)d_in[3];
    float* out = (float*)d_out;

    init_out_kernel<<<(out_size + 255) / 256, 256>>>(bc, out, out_size);
    hist_kernel<<<NWARP_, 32>>>((const float4*)x, be, fr, out);
}